// round 2
// baseline (speedup 1.0000x reference)
#include <cuda_runtime.h>

// SIR ODE, RK4, B=65536 systems, NUM_T=200 outputs, 8 substeps per interval.
// Each thread integrates TWO systems packed into f32x2 (Blackwell dual-fp32),
// state fully register-resident, output staged 4 timesteps -> STG.128 x3.
// Launch: 128 blocks x 256 threads = single wave, 2 warps/SMSP.

#define NUM_T_C    200
#define SUBSTEPS_C 8

typedef unsigned long long u64;

__device__ __forceinline__ u64 pk2(float lo, float hi) {
    u64 r;
    asm("mov.b64 %0, {%1, %2};" : "=l"(r) : "f"(lo), "f"(hi));
    return r;
}
__device__ __forceinline__ void upk2(u64 v, float& lo, float& hi) {
    asm("mov.b64 {%0, %1}, %2;" : "=f"(lo), "=f"(hi) : "l"(v));
}
__device__ __forceinline__ u64 fma2(u64 a, u64 b, u64 c) {
    u64 d;
    asm("fma.rn.f32x2 %0, %1, %2, %3;" : "=l"(d) : "l"(a), "l"(b), "l"(c));
    return d;
}
__device__ __forceinline__ u64 mul2(u64 a, u64 b) {
    u64 d;
    asm("mul.rn.f32x2 %0, %1, %2;" : "=l"(d) : "l"(a), "l"(b));
    return d;
}
__device__ __forceinline__ u64 add2(u64 a, u64 b) {
    u64 d;
    asm("add.rn.f32x2 %0, %1, %2;" : "=l"(d) : "l"(a), "l"(b));
    return d;
}

__global__ __launch_bounds__(256)
void sir_rk4_kernel(const float4* __restrict__ params,
                    float* __restrict__ out,
                    int nPairs) {
    const int t = blockIdx.x * blockDim.x + threadIdx.x;
    if (t >= nPairs) return;

    const int b0 = t;
    const int b1 = t + nPairs;

    const float4 pa = params[b0];
    const float4 pb = params[b1];

    const u64 beta  = pk2(pa.x, pb.x);
    const u64 gamma = pk2(pa.y, pb.y);
    u64 S = pk2(pa.z, pb.z);
    u64 I = pk2(pa.w, pb.w);

    // R0 = 1 - S0 - I0 (fma with -1: single-rounding subtraction)
    const u64 m1  = pk2(-1.0f, -1.0f);
    const u64 one = pk2(1.0f, 1.0f);
    u64 R = fma2(S, m1, one);
    R = fma2(I, m1, R);

    // Step constants
    const float dtf  = 100.0f / 199.0f;    // linspace spacing
    const float hf   = dtf / (float)SUBSTEPS_C;
    const float h2f  = 0.5f * hf;
    const float h6f  = hf / 6.0f;

    const u64 ch2  = pk2( h2f,  h2f);
    const u64 ch2n = pk2(-h2f, -h2f);
    const u64 ch   = pk2( hf,   hf);
    const u64 chn  = pk2(-hf,  -hf);
    const u64 ch6  = pk2( h6f,  h6f);
    const u64 ch6n = pk2(-h6f, -h6f);
    const u64 c2   = pk2(2.0f, 2.0f);

    // One full dt step = 8 RK4 substeps.
    // dS = -bSI, dI = bSI - gI, dR = gI; f() never reads R.
    auto rk4_8 = [&]() {
#pragma unroll
        for (int ss = 0; ss < SUBSTEPS_C; ss++) {
            // stage 1
            u64 bs1 = mul2(mul2(beta, S), I);
            u64 g1  = mul2(gamma, I);
            u64 d1  = fma2(g1, m1, bs1);          // dI1 = bSI1 - gI1
            u64 yS  = fma2(bs1, ch2n, S);         // S + h/2 * (-bSI1)
            u64 yI  = fma2(d1, ch2, I);
            // stage 2
            u64 bs2 = mul2(mul2(beta, yS), yI);
            u64 g2  = mul2(gamma, yI);
            u64 d2  = fma2(g2, m1, bs2);
            yS = fma2(bs2, ch2n, S);
            yI = fma2(d2, ch2, I);
            // stage 3
            u64 bs3 = mul2(mul2(beta, yS), yI);
            u64 g3  = mul2(gamma, yI);
            u64 d3  = fma2(g3, m1, bs3);
            yS = fma2(bs3, chn, S);
            yI = fma2(d3, ch, I);
            // stage 4
            u64 bs4 = mul2(mul2(beta, yS), yI);
            u64 g4  = mul2(gamma, yI);
            u64 d4  = fma2(g4, m1, bs4);
            // combine: y += h/6 * (k1 + 2*(k2+k3) + k4)
            u64 sb = add2(bs2, bs3);
            sb = fma2(sb, c2, bs1);
            sb = add2(sb, bs4);
            S  = fma2(sb, ch6n, S);               // kS = -bSI

            u64 si = add2(d2, d3);
            si = fma2(si, c2, d1);
            si = add2(si, d4);
            I  = fma2(si, ch6, I);

            u64 sr = add2(g2, g3);
            sr = fma2(sr, c2, g1);
            sr = add2(sr, g4);
            R  = fma2(sr, ch6, R);
        }
    };

    // Output staging: 4 timesteps (12 floats) per system -> 3x float4 stores.
    __align__(16) float bufA[12];
    __align__(16) float bufB[12];

    float4* outA = (float4*)(out + (size_t)b0 * (NUM_T_C * 3));
    float4* outB = (float4*)(out + (size_t)b1 * (NUM_T_C * 3));

    auto stash = [&](int o) {
        upk2(S, bufA[o + 0], bufB[o + 0]);
        upk2(I, bufA[o + 1], bufB[o + 1]);
        upk2(R, bufA[o + 2], bufB[o + 2]);
    };
    auto flush = [&](int g) {
        const float4* fa = (const float4*)bufA;
        const float4* fb = (const float4*)bufB;
#pragma unroll
        for (int q = 0; q < 3; q++) {
            outA[g * 3 + q] = fa[q];
            outB[g * 3 + q] = fb[q];
        }
    };

    // Group 0: y0 + 3 computed steps (timesteps 0..3)
    stash(0);
#pragma unroll
    for (int s = 0; s < 3; s++) {
        rk4_8();
        stash(3 + s * 3);
    }
    flush(0);

    // Groups 1..49: 4 computed steps each (timesteps 4g..4g+3). 200 = 4*50.
    for (int g = 1; g < 50; g++) {
#pragma unroll
        for (int s = 0; s < 4; s++) {
            rk4_8();
            stash(s * 3);
        }
        flush(g);
    }
}

extern "C" void kernel_launch(void* const* d_in, const int* in_sizes, int n_in,
                              void* d_out, int out_size) {
    const float4* params = (const float4*)d_in[0];
    float* out = (float*)d_out;

    const int B = in_sizes[0] / 4;   // 65536 systems, 4 params each
    const int nPairs = B / 2;        // two systems per thread (f32x2 packed)

    const int threads = 256;
    const int blocks = (nPairs + threads - 1) / threads;   // 128 blocks: single wave
    sir_rk4_kernel<<<blocks, threads>>>(params, out, nPairs);
}

// round 4
// speedup vs baseline: 1.2213x; 1.2213x over previous
#include <cuda_runtime.h>

// SIR ODE RK4, B=65536, NUM_T=200, 8 substeps/interval.
// Two systems per thread packed in f32x2 (Blackwell dual-fp32).
// Algebraic cuts vs round-2:
//   (a) R not integrated: RK4 conserves S+I+R exactly -> R = 1-S-I at output.
//   (b) transform s = beta*S: bSI = s*I (1 mul, not 2); stage advances use
//       per-thread constants -(h/2)b, -h*b, -(h/6)b; S recovered as s*(1/b)
//       only at the 200 output points. beta==0 guarded via max(beta,1e-20).
// 26 f32x2 fma-pipe ops per substep (was 34).

#define NUM_T_C    200
#define SUBSTEPS_C 8

typedef unsigned long long u64;

__device__ __forceinline__ u64 pk2(float lo, float hi) {
    u64 r;
    asm("mov.b64 %0, {%1, %2};" : "=l"(r) : "f"(lo), "f"(hi));
    return r;
}
__device__ __forceinline__ void upk2(u64 v, float& lo, float& hi) {
    asm("mov.b64 {%0, %1}, %2;" : "=f"(lo), "=f"(hi) : "l"(v));
}
__device__ __forceinline__ u64 fma2(u64 a, u64 b, u64 c) {
    u64 d;
    asm("fma.rn.f32x2 %0, %1, %2, %3;" : "=l"(d) : "l"(a), "l"(b), "l"(c));
    return d;
}
__device__ __forceinline__ u64 mul2(u64 a, u64 b) {
    u64 d;
    asm("mul.rn.f32x2 %0, %1, %2;" : "=l"(d) : "l"(a), "l"(b));
    return d;
}
__device__ __forceinline__ u64 add2(u64 a, u64 b) {
    u64 d;
    asm("add.rn.f32x2 %0, %1, %2;" : "=l"(d) : "l"(a), "l"(b));
    return d;
}

__global__ __launch_bounds__(256)
void sir_rk4_kernel(const float4* __restrict__ params,
                    float* __restrict__ out,
                    int nPairs) {
    const int t = blockIdx.x * blockDim.x + threadIdx.x;
    if (t >= nPairs) return;

    const int b0 = t;
    const int b1 = t + nPairs;

    const float4 pa = params[b0];
    const float4 pb = params[b1];

    // beta guard: beta==0 -> s==0 forever, S_out = s*rbeta = S0 via s0 = be*S0.
    const float beA = fmaxf(pa.x, 1e-20f);
    const float beB = fmaxf(pb.x, 1e-20f);

    const u64 beta  = pk2(beA, beB);
    const u64 rbeta = pk2(1.0f / beA, 1.0f / beB);
    const u64 gamma = pk2(pa.y, pb.y);

    u64 s = mul2(beta, pk2(pa.z, pb.z));   // s = beta * S
    u64 I = pk2(pa.w, pb.w);

    const u64 m1  = pk2(-1.0f, -1.0f);
    const u64 one = pk2(1.0f, 1.0f);

    // Step constants
    const float dtf  = 100.0f / 199.0f;
    const float hf   = dtf / (float)SUBSTEPS_C;
    const float h2f  = 0.5f * hf;
    const float h6f  = hf / 6.0f;

    const u64 ch2  = pk2(h2f, h2f);
    const u64 ch   = pk2(hf,  hf);
    const u64 ch6  = pk2(h6f, h6f);
    const u64 c2   = pk2(2.0f, 2.0f);

    // Per-thread beta-scaled step constants (negative: dS = -bSI)
    const u64 cb2n = mul2(beta, pk2(-h2f, -h2f));
    const u64 cbn  = mul2(beta, pk2(-hf,  -hf));
    const u64 cb6n = mul2(beta, pk2(-h6f, -h6f));

    // One full dt step = 8 RK4 substeps on (s, I).
    auto rk4_8 = [&]() {
#pragma unroll
        for (int ss = 0; ss < SUBSTEPS_C; ss++) {
            // stage 1
            u64 bs1 = mul2(s, I);
            u64 g1  = mul2(gamma, I);
            u64 d1  = fma2(g1, m1, bs1);       // dI = sI - gI
            u64 ys  = fma2(bs1, cb2n, s);
            u64 yI  = fma2(d1, ch2, I);
            // stage 2
            u64 bs2 = mul2(ys, yI);
            u64 g2  = mul2(gamma, yI);
            u64 d2  = fma2(g2, m1, bs2);
            ys = fma2(bs2, cb2n, s);
            yI = fma2(d2, ch2, I);
            // stage 3
            u64 bs3 = mul2(ys, yI);
            u64 g3  = mul2(gamma, yI);
            u64 d3  = fma2(g3, m1, bs3);
            ys = fma2(bs3, cbn, s);
            yI = fma2(d3, ch, I);
            // stage 4
            u64 bs4 = mul2(ys, yI);
            u64 g4  = mul2(gamma, yI);
            u64 d4  = fma2(g4, m1, bs4);
            // combine
            u64 sb = add2(bs2, bs3);
            sb = fma2(sb, c2, bs1);
            sb = add2(sb, bs4);
            s  = fma2(sb, cb6n, s);

            u64 si = add2(d2, d3);
            si = fma2(si, c2, d1);
            si = add2(si, d4);
            I  = fma2(si, ch6, I);
        }
    };

    // Output staging: 4 timesteps (12 floats) per system -> 3x float4 stores.
    __align__(16) float bufA[12];
    __align__(16) float bufB[12];

    float4* outA = (float4*)(out + (size_t)b0 * (NUM_T_C * 3));
    float4* outB = (float4*)(out + (size_t)b1 * (NUM_T_C * 3));

    auto stash = [&](int o) {
        u64 S = mul2(s, rbeta);                 // recover S
        u64 R = fma2(S, m1, one);               // 1 - S
        R = fma2(I, m1, R);                     // 1 - S - I
        upk2(S, bufA[o + 0], bufB[o + 0]);
        upk2(I, bufA[o + 1], bufB[o + 1]);
        upk2(R, bufA[o + 2], bufB[o + 2]);
    };
    auto flush = [&](int g) {
        const float4* fa = (const float4*)bufA;
        const float4* fb = (const float4*)bufB;
#pragma unroll
        for (int q = 0; q < 3; q++) {
            outA[g * 3 + q] = fa[q];
            outB[g * 3 + q] = fb[q];
        }
    };

    // Group 0: y0 + 3 computed steps (timesteps 0..3)
    stash(0);
#pragma unroll
    for (int sgi = 0; sgi < 3; sgi++) {
        rk4_8();
        stash(3 + sgi * 3);
    }
    flush(0);

    // Groups 1..49: 4 computed steps each. 200 = 4*50.
    for (int g = 1; g < 50; g++) {
#pragma unroll
        for (int sgi = 0; sgi < 4; sgi++) {
            rk4_8();
            stash(sgi * 3);
        }
        flush(g);
    }
}

extern "C" void kernel_launch(void* const* d_in, const int* in_sizes, int n_in,
                              void* d_out, int out_size) {
    const float4* params = (const float4*)d_in[0];
    float* out = (float*)d_out;

    const int B = in_sizes[0] / 4;
    const int nPairs = B / 2;

    const int threads = 256;
    const int blocks = (nPairs + threads - 1) / threads;
    sir_rk4_kernel<<<blocks, threads>>>(params, out, nPairs);
}